// round 5
// baseline (speedup 1.0000x reference)
#include <cuda_runtime.h>
#include <math_constants.h>
#include <cstdint>

#define BB 8
#define N1C 2048
#define N2C 2048
#define DD 120

// ---------------- scratch (device globals; no allocation) ----------------
__device__ float g_Q[(size_t)BB * N1C * DD];   // [b][n1][d]
__device__ float g_K[(size_t)BB * N2C * DD];   // [b][n2][d]
__device__ float g_V[(size_t)BB * N2C * DD];   // [b][n2][d]
__device__ float g_M[BB * N1C];                // row max
__device__ float g_L[BB * N1C];                // row sum-exp

// ---------------- tf32 mma.sync helper (sm_80+ baseline PTX) ----------------
__device__ __forceinline__ void mma_tf32(float* c,
    uint32_t a0, uint32_t a1, uint32_t a2, uint32_t a3,
    uint32_t b0, uint32_t b1)
{
    asm volatile(
        "mma.sync.aligned.m16n8k8.row.col.f32.tf32.tf32.f32 "
        "{%0,%1,%2,%3}, {%4,%5,%6,%7}, {%8,%9}, {%0,%1,%2,%3};"
        : "+f"(c[0]), "+f"(c[1]), "+f"(c[2]), "+f"(c[3])
        : "r"(a0), "r"(a1), "r"(a2), "r"(a3), "r"(b0), "r"(b1));
}

// split fp32 -> tf32 hi (exact) + tf32 lo (quantized remainder)
__device__ __forceinline__ void tf32_split(float v, uint32_t& h, uint32_t& l) {
    uint32_t hv = __float_as_uint(v) & 0xffffe000u;
    h = hv;
    float lo = v - __uint_as_float(hv);
    l = __float_as_uint(lo) & 0xffffe000u;
}

// ================= kernel 1: QKV projection (natural-layout outputs) =================
#define PROJ_XS  (64 * 40)
#define PROJ_WS  (40 * 132)
#define PROJ_SMEM ((PROJ_XS + PROJ_WS) * 4)

__global__ __launch_bounds__(256) void proj_kernel(
    const float* __restrict__ x1, const float* __restrict__ x2,
    const float* __restrict__ Wq, const float* __restrict__ Wk,
    const float* __restrict__ Wv)
{
    extern __shared__ float sm[];
    float* Xs = sm;               // [r][40]
    float* Ws = sm + PROJ_XS;     // [d][132], cols >=120 zero

    const int which = blockIdx.y;
    const float* X = (which == 0) ? x1 : x2;
    const float* W = (which == 0) ? Wq : (which == 1 ? Wk : Wv);
    float* OUT = (which == 0) ? g_Q : (which == 1 ? g_K : g_V);

    const int row0 = blockIdx.x * 64;
    const int tid = threadIdx.x;
    const int tx = tid & 15, ty = tid >> 4;

    float acc[4][8];
    #pragma unroll
    for (int r = 0; r < 4; r++)
        #pragma unroll
        for (int c = 0; c < 8; c++) acc[r][c] = 0.f;

    for (int d0 = 0; d0 < DD; d0 += 40) {
        __syncthreads();
        #pragma unroll
        for (int t = 0; t < 10; t++) {
            int idx = t * 256 + tid;
            int r = idx / 40, d = idx % 40;
            Xs[idx] = X[(size_t)(row0 + r) * DD + d0 + d];
        }
        #pragma unroll
        for (int t = 0; t < 20; t++) {
            int idx = t * 256 + tid;
            int d = idx >> 7, e = idx & 127;
            Ws[d * 132 + e] = (e < DD) ? W[(size_t)(d0 + d) * DD + e] : 0.f;
        }
        __syncthreads();

        #pragma unroll 4
        for (int d = 0; d < 40; d++) {
            float4 wa = *(const float4*)&Ws[d * 132 + 4 * tx];
            float4 wb = *(const float4*)&Ws[d * 132 + 64 + 4 * tx];
            float xv[4];
            #pragma unroll
            for (int r = 0; r < 4; r++) xv[r] = Xs[(4 * ty + r) * 40 + d];
            #pragma unroll
            for (int r = 0; r < 4; r++) {
                acc[r][0] = fmaf(xv[r], wa.x, acc[r][0]);
                acc[r][1] = fmaf(xv[r], wa.y, acc[r][1]);
                acc[r][2] = fmaf(xv[r], wa.z, acc[r][2]);
                acc[r][3] = fmaf(xv[r], wa.w, acc[r][3]);
                acc[r][4] = fmaf(xv[r], wb.x, acc[r][4]);
                acc[r][5] = fmaf(xv[r], wb.y, acc[r][5]);
                acc[r][6] = fmaf(xv[r], wb.z, acc[r][6]);
                acc[r][7] = fmaf(xv[r], wb.w, acc[r][7]);
            }
        }
    }

    #pragma unroll
    for (int r = 0; r < 4; r++) {
        size_t base = (size_t)(row0 + 4 * ty + r) * DD;
        *(float4*)&OUT[base + 4 * tx] =
            make_float4(acc[r][0], acc[r][1], acc[r][2], acc[r][3]);
        if (64 + 4 * tx + 3 < DD)
            *(float4*)&OUT[base + 64 + 4 * tx] =
                make_float4(acc[r][4], acc[r][5], acc[r][6], acc[r][7]);
    }
}

// ================= kernel 2: scores via mma.sync tf32 split =================
// grid (16, 8), block 256 (8 warps). Block tile: 128 i x 64 j streamed.
// warp wid: m0 = 32*(wid>>1), n0 = 32*(wid&1): warp computes m32 x n32.
// smem: Qs[128][124] + Ks[64][124] + Ss[128][66]
#define SC_KS_OFF (128 * 124)
#define SC_SS_OFF (SC_KS_OFF + 64 * 124)
#define SC_SMEM ((SC_SS_OFF + 128 * 66) * 4)

__global__ __launch_bounds__(256, 1) void score_kernel(
    const int* __restrict__ mask, float* __restrict__ attn)
{
    extern __shared__ float sm[];
    float* Qs = sm;                 // [128][124]
    float* Ks = sm + SC_KS_OFF;     // [64][124]
    float* Ss = sm + SC_SS_OFF;     // [128][66]

    const int b  = blockIdx.y;
    const int i0 = blockIdx.x * 128;
    const int tid  = threadIdx.x;
    const int wid  = tid >> 5;
    const int lane = tid & 31;
    const int g    = lane >> 2;     // 0..7
    const int tig  = lane & 3;      // 0..3
    const int m0 = 32 * (wid >> 1);
    const int n0 = 32 * (wid & 1);

    // load Q tile [128][120] into stride-124 smem
    {
        const float* gq = g_Q + ((size_t)(b * N1C + i0)) * DD;
        #pragma unroll
        for (int it = 0; it < 16; it++) {
            int idx = it * 256 + tid;          // 128 x 32 slots
            int r = idx >> 5, ch = idx & 31;
            if (ch < 30)
                *(float4*)&Qs[r * 124 + ch * 4] =
                    *(const float4*)&gq[(size_t)r * DD + ch * 4];
        }
    }

    const float scale = 0.09128709291752768f;  // 1/sqrt(120)
    float mrun[16], lrun[16];
    #pragma unroll
    for (int k = 0; k < 16; k++) { mrun[k] = -CUDART_INF_F; lrun[k] = 0.f; }

    for (int t = 0; t < 32; t++) {
        const int j0 = t * 64;
        __syncthreads();   // Ks/Ss reusable
        // load K tile [64][120]
        {
            const float* gk = g_K + ((size_t)(b * N2C + j0)) * DD;
            #pragma unroll
            for (int it = 0; it < 8; it++) {
                int idx = it * 256 + tid;      // 64 x 32 slots
                int r = idx >> 5, ch = idx & 31;
                if (ch < 30)
                    *(float4*)&Ks[r * 124 + ch * 4] =
                        *(const float4*)&gk[(size_t)r * DD + ch * 4];
            }
        }
        __syncthreads();

        float acc[2][4][4];
        #pragma unroll
        for (int m = 0; m < 2; m++)
            #pragma unroll
            for (int n = 0; n < 4; n++)
                #pragma unroll
                for (int q = 0; q < 4; q++) acc[m][n][q] = 0.f;

        #pragma unroll 5
        for (int k8 = 0; k8 < 15; k8++) {
            const int k0 = k8 * 8;
            uint32_t ah[2][4], al[2][4];
            #pragma unroll
            for (int m = 0; m < 2; m++) {
                int r0 = (m0 + 16 * m + g) * 124 + k0 + tig;
                int r1 = (m0 + 16 * m + 8 + g) * 124 + k0 + tig;
                tf32_split(Qs[r0],     ah[m][0], al[m][0]);
                tf32_split(Qs[r1],     ah[m][1], al[m][1]);
                tf32_split(Qs[r0 + 4], ah[m][2], al[m][2]);
                tf32_split(Qs[r1 + 4], ah[m][3], al[m][3]);
            }
            #pragma unroll
            for (int n = 0; n < 4; n++) {
                int kb = (n0 + 8 * n + g) * 124 + k0 + tig;
                uint32_t bh0, bl0, bh1, bl1;
                tf32_split(Ks[kb],     bh0, bl0);
                tf32_split(Ks[kb + 4], bh1, bl1);
                #pragma unroll
                for (int m = 0; m < 2; m++) {
                    mma_tf32(acc[m][n], ah[m][0], ah[m][1], ah[m][2], ah[m][3], bh0, bh1);
                    mma_tf32(acc[m][n], al[m][0], al[m][1], al[m][2], al[m][3], bh0, bh1);
                    mma_tf32(acc[m][n], ah[m][0], ah[m][1], ah[m][2], ah[m][3], bl0, bl1);
                }
            }
        }

        // stage D to Ss
        #pragma unroll
        for (int m = 0; m < 2; m++)
            #pragma unroll
            for (int n = 0; n < 4; n++) {
                int row = m0 + 16 * m + g;
                int col = n0 + 8 * n + 2 * tig;
                *(float2*)&Ss[row * 66 + col]       = make_float2(acc[m][n][0], acc[m][n][1]);
                *(float2*)&Ss[(row + 8) * 66 + col] = make_float2(acc[m][n][2], acc[m][n][3]);
            }
        __syncthreads();

        // phase 2: coalesced mask + scale + online stats + raw-score store
        #pragma unroll
        for (int k = 0; k < 16; k++) {
            int r = (k << 3) + wid;
            int gi = i0 + r;
            size_t mb = ((size_t)(b * N1C + gi)) * N2C + j0;
            float raw0 = Ss[r * 66 + lane];
            float raw1 = Ss[r * 66 + 32 + lane];
            int mv0 = mask[mb + lane];
            int mv1 = mask[mb + 32 + lane];
            float s0 = mv0 ? raw0 * scale : -CUDART_INF_F;
            float s1 = mv1 ? raw1 * scale : -CUDART_INF_F;
            attn[mb + lane]      = s0;
            attn[mb + 32 + lane] = s1;

            float tmax = fmaxf(s0, s1);
            #pragma unroll
            for (int o = 16; o; o >>= 1)
                tmax = fmaxf(tmax, __shfl_xor_sync(0xffffffffu, tmax, o));
            float mnew = fmaxf(mrun[k], tmax);

            float se = __expf(s0 - mnew) + __expf(s1 - mnew);
            #pragma unroll
            for (int o = 16; o; o >>= 1)
                se += __shfl_xor_sync(0xffffffffu, se, o);

            lrun[k] = lrun[k] * __expf(mrun[k] - mnew) + se;
            mrun[k] = mnew;
        }
    }

    if (lane == 0) {
        #pragma unroll
        for (int k = 0; k < 16; k++) {
            int gi = b * N1C + i0 + (k << 3) + wid;
            g_M[gi] = mrun[k];
            g_L[gi] = lrun[k];
        }
    }
}

// ================= kernel 3: normalize attn + O = P.V via mma.sync =================
// grid (16, 8), block 256. Block tile: 128 i x 120 e, j streamed in 64 chunks.
// warp wid: m0 = 32*(wid>>1), e0 = 64*(wid&1): warp computes m32 x n64.
// smem: Vs[64][120] + Ps[128][68] + mrow[128] + lirow[128]
#define PV_PS_OFF (64 * 120)
#define PV_MR_OFF (PV_PS_OFF + 128 * 68)
#define PV_SMEM ((PV_MR_OFF + 256) * 4)

__global__ __launch_bounds__(256) void pv_kernel(
    float* __restrict__ attn, float* __restrict__ out)
{
    extern __shared__ float sm[];
    float* Vs    = sm;                  // [j=64][e stride 120]
    float* Ps    = sm + PV_PS_OFF;      // [128][68]
    float* mrow  = sm + PV_MR_OFF;      // [128]
    float* lirow = mrow + 128;          // [128]

    const int b  = blockIdx.y;
    const int i0 = blockIdx.x * 128;
    const int tid  = threadIdx.x;
    const int wid  = tid >> 5;
    const int lane = tid & 31;
    const int g    = lane >> 2;
    const int tig  = lane & 3;
    const int m0 = 32 * (wid >> 1);
    const int e0 = 64 * (wid & 1);

    if (tid < 128) {
        mrow[tid]  = g_M[b * N1C + i0 + tid];
        lirow[tid] = 1.0f / g_L[b * N1C + i0 + tid];
    }

    float acc[2][8][4];
    #pragma unroll
    for (int m = 0; m < 2; m++)
        #pragma unroll
        for (int n = 0; n < 8; n++)
            #pragma unroll
            for (int q = 0; q < 4; q++) acc[m][n][q] = 0.f;

    for (int t = 0; t < 32; t++) {
        const int j0 = t * 64;
        __syncthreads();
        // V tile [64][120], stride 120
        {
            const float* gv = g_V + ((size_t)(b * N2C + j0)) * DD;
            #pragma unroll
            for (int it = 0; it < 8; it++) {
                int idx = it * 256 + tid;
                int r = idx >> 5, ch = idx & 31;
                if (ch < 30)
                    *(float4*)&Vs[r * 120 + ch * 4] =
                        *(const float4*)&gv[(size_t)r * DD + ch * 4];
            }
        }
        // P generation: raw -> exp(s-m)*li, write gmem + stash in Ps
        #pragma unroll
        for (int it = 0; it < 8; it++) {
            int f4 = it * 256 + tid;            // 2048 float4s: 128 rows x 16
            int r  = f4 >> 4;
            int c4 = (f4 & 15) * 4;
            size_t gidx = ((size_t)(b * N1C + i0 + r)) * N2C + j0 + c4;
            float4 sv = *(const float4*)&attn[gidx];
            float m = mrow[r], li = lirow[r];
            float4 p;
            p.x = __expf(sv.x - m) * li;
            p.y = __expf(sv.y - m) * li;
            p.z = __expf(sv.z - m) * li;
            p.w = __expf(sv.w - m) * li;
            *(float4*)&attn[gidx] = p;
            *(float4*)&Ps[r * 68 + c4] = p;
        }
        __syncthreads();

        #pragma unroll 4
        for (int k8 = 0; k8 < 8; k8++) {
            const int k0 = k8 * 8;
            uint32_t ah[2][4], al[2][4];
            #pragma unroll
            for (int m = 0; m < 2; m++) {
                int r0 = (m0 + 16 * m + g) * 68 + k0 + tig;
                int r1 = (m0 + 16 * m + 8 + g) * 68 + k0 + tig;
                tf32_split(Ps[r0],     ah[m][0], al[m][0]);
                tf32_split(Ps[r1],     ah[m][1], al[m][1]);
                tf32_split(Ps[r0 + 4], ah[m][2], al[m][2]);
                tf32_split(Ps[r1 + 4], ah[m][3], al[m][3]);
            }
            #pragma unroll
            for (int n = 0; n < 8; n++) {
                int e = e0 + 8 * n + g;
                uint32_t bh0, bl0, bh1, bl1;
                float v0 = (e < DD) ? Vs[(k0 + tig) * 120 + e] : 0.f;
                float v1 = (e < DD) ? Vs[(k0 + tig + 4) * 120 + e] : 0.f;
                tf32_split(v0, bh0, bl0);
                tf32_split(v1, bh1, bl1);
                #pragma unroll
                for (int m = 0; m < 2; m++) {
                    mma_tf32(acc[m][n], ah[m][0], ah[m][1], ah[m][2], ah[m][3], bh0, bh1);
                    mma_tf32(acc[m][n], al[m][0], al[m][1], al[m][2], al[m][3], bh0, bh1);
                    mma_tf32(acc[m][n], ah[m][0], ah[m][1], ah[m][2], ah[m][3], bl0, bl1);
                }
            }
        }
    }

    // final O store
    #pragma unroll
    for (int m = 0; m < 2; m++)
        #pragma unroll
        for (int n = 0; n < 8; n++) {
            int e = e0 + 8 * n + 2 * tig;
            if (e < DD) {
                int i = i0 + m0 + 16 * m + g;
                *(float2*)&out[((size_t)(b * N1C + i)) * DD + e] =
                    make_float2(acc[m][n][0], acc[m][n][1]);
                *(float2*)&out[((size_t)(b * N1C + i + 8)) * DD + e] =
                    make_float2(acc[m][n][2], acc[m][n][3]);
            }
        }
}

// ================= launch =================
extern "C" void kernel_launch(void* const* d_in, const int* in_sizes, int n_in,
                              void* d_out, int out_size)
{
    const float* x1  = (const float*)d_in[0];
    const float* x2  = (const float*)d_in[1];
    const int*   msk = (const int*)  d_in[2];
    const float* Wq  = (const float*)d_in[3];
    const float* Wk  = (const float*)d_in[4];
    const float* Wv  = (const float*)d_in[5];

    float* outO = (float*)d_out;                    // [B,N1,D]
    float* outP = outO + (size_t)BB * N1C * DD;     // [B,N1,N2]

    cudaFuncSetAttribute(proj_kernel,  cudaFuncAttributeMaxDynamicSharedMemorySize, PROJ_SMEM);
    cudaFuncSetAttribute(score_kernel, cudaFuncAttributeMaxDynamicSharedMemorySize, SC_SMEM);
    cudaFuncSetAttribute(pv_kernel,    cudaFuncAttributeMaxDynamicSharedMemorySize, PV_SMEM);

    proj_kernel <<<dim3((BB * N1C) / 64, 3), 256, PROJ_SMEM>>>(x1, x2, Wq, Wk, Wv);
    score_kernel<<<dim3(N1C / 128, BB), 256, SC_SMEM>>>(msk, outP);
    pv_kernel   <<<dim3(N1C / 128, BB), 256, PV_SMEM>>>(outP, outO);
}

// round 7
// speedup vs baseline: 1.1243x; 1.1243x over previous
#include <cuda_runtime.h>
#include <cuda_bf16.h>
#include <math_constants.h>
#include <cstdint>

#define BB 8
#define N1C 2048
#define N2C 2048
#define DD 120

// ---------------- scratch (device globals; no allocation) ----------------
__device__ float g_Q[(size_t)BB * N1C * DD];   // [b][n1][d]
__device__ float g_K[(size_t)BB * N2C * DD];   // [b][n2][d]
__device__ float g_V[(size_t)BB * N2C * DD];   // [b][n2][d]
__device__ float g_M[BB * N1C];                // row max
__device__ float g_L[BB * N1C];                // row sum-exp

// ---------------- mma helpers ----------------
__device__ __forceinline__ void mma_tf32(float* c,
    uint32_t a0, uint32_t a1, uint32_t a2, uint32_t a3,
    uint32_t b0, uint32_t b1)
{
    asm volatile(
        "mma.sync.aligned.m16n8k8.row.col.f32.tf32.tf32.f32 "
        "{%0,%1,%2,%3}, {%4,%5,%6,%7}, {%8,%9}, {%0,%1,%2,%3};"
        : "+f"(c[0]), "+f"(c[1]), "+f"(c[2]), "+f"(c[3])
        : "r"(a0), "r"(a1), "r"(a2), "r"(a3), "r"(b0), "r"(b1));
}
__device__ __forceinline__ void mma_bf16(float* c,
    uint32_t a0, uint32_t a1, uint32_t a2, uint32_t a3,
    uint32_t b0, uint32_t b1)
{
    asm volatile(
        "mma.sync.aligned.m16n8k16.row.col.f32.bf16.bf16.f32 "
        "{%0,%1,%2,%3}, {%4,%5,%6,%7}, {%8,%9}, {%0,%1,%2,%3};"
        : "+f"(c[0]), "+f"(c[1]), "+f"(c[2]), "+f"(c[3])
        : "r"(a0), "r"(a1), "r"(a2), "r"(a3), "r"(b0), "r"(b1));
}

// fp32 -> tf32 hi (trunc) + tf32 lo (trunc remainder), as floats
__device__ __forceinline__ void tsplit(float v, float& h, float& l) {
    h = __uint_as_float(__float_as_uint(v) & 0xffffe000u);
    l = __uint_as_float(__float_as_uint(v - h) & 0xffffe000u);
}

// two fp32 -> packed bf16x2 hi + packed bf16x2 lo (x0 in low half)
__device__ __forceinline__ void bsplit2(float x0, float x1, uint32_t& h, uint32_t& l) {
    __nv_bfloat162 hh = __floats2bfloat162_rn(x0, x1);
    float h0 = __bfloat162float(hh.x), h1 = __bfloat162float(hh.y);
    __nv_bfloat162 ll = __floats2bfloat162_rn(x0 - h0, x1 - h1);
    h = *(uint32_t*)&hh;
    l = *(uint32_t*)&ll;
}

// ================= kernel 1: QKV projection =================
#define PROJ_XS  (64 * 40)
#define PROJ_WS  (40 * 132)
#define PROJ_SMEM ((PROJ_XS + PROJ_WS) * 4)

__global__ __launch_bounds__(256) void proj_kernel(
    const float* __restrict__ x1, const float* __restrict__ x2,
    const float* __restrict__ Wq, const float* __restrict__ Wk,
    const float* __restrict__ Wv)
{
    extern __shared__ float sm[];
    float* Xs = sm;               // [r][40]
    float* Ws = sm + PROJ_XS;     // [d][132]

    const int which = blockIdx.y;
    const float* X = (which == 0) ? x1 : x2;
    const float* W = (which == 0) ? Wq : (which == 1 ? Wk : Wv);
    float* OUT = (which == 0) ? g_Q : (which == 1 ? g_K : g_V);

    const int row0 = blockIdx.x * 64;
    const int tid = threadIdx.x;
    const int tx = tid & 15, ty = tid >> 4;

    float acc[4][8];
    #pragma unroll
    for (int r = 0; r < 4; r++)
        #pragma unroll
        for (int c = 0; c < 8; c++) acc[r][c] = 0.f;

    for (int d0 = 0; d0 < DD; d0 += 40) {
        __syncthreads();
        #pragma unroll
        for (int t = 0; t < 10; t++) {
            int idx = t * 256 + tid;
            int r = idx / 40, d = idx % 40;
            Xs[idx] = X[(size_t)(row0 + r) * DD + d0 + d];
        }
        #pragma unroll
        for (int t = 0; t < 20; t++) {
            int idx = t * 256 + tid;
            int d = idx >> 7, e = idx & 127;
            Ws[d * 132 + e] = (e < DD) ? W[(size_t)(d0 + d) * DD + e] : 0.f;
        }
        __syncthreads();

        #pragma unroll 4
        for (int d = 0; d < 40; d++) {
            float4 wa = *(const float4*)&Ws[d * 132 + 4 * tx];
            float4 wb = *(const float4*)&Ws[d * 132 + 64 + 4 * tx];
            float xv[4];
            #pragma unroll
            for (int r = 0; r < 4; r++) xv[r] = Xs[(4 * ty + r) * 40 + d];
            #pragma unroll
            for (int r = 0; r < 4; r++) {
                acc[r][0] = fmaf(xv[r], wa.x, acc[r][0]);
                acc[r][1] = fmaf(xv[r], wa.y, acc[r][1]);
                acc[r][2] = fmaf(xv[r], wa.z, acc[r][2]);
                acc[r][3] = fmaf(xv[r], wa.w, acc[r][3]);
                acc[r][4] = fmaf(xv[r], wb.x, acc[r][4]);
                acc[r][5] = fmaf(xv[r], wb.y, acc[r][5]);
                acc[r][6] = fmaf(xv[r], wb.z, acc[r][6]);
                acc[r][7] = fmaf(xv[r], wb.w, acc[r][7]);
            }
        }
    }

    #pragma unroll
    for (int r = 0; r < 4; r++) {
        size_t base = (size_t)(row0 + 4 * ty + r) * DD;
        *(float4*)&OUT[base + 4 * tx] =
            make_float4(acc[r][0], acc[r][1], acc[r][2], acc[r][3]);
        if (64 + 4 * tx + 3 < DD)
            *(float4*)&OUT[base + 64 + 4 * tx] =
                make_float4(acc[r][4], acc[r][5], acc[r][6], acc[r][7]);
    }
}

// ================= kernel 2: scores, tf32 split-ahead =================
// smem (floats): Qh[128][124], Ql[128][124], Kh[64][124], Kl[64][124], Ss[128][66]
#define SC_QL_OFF (128 * 124)
#define SC_KH_OFF (SC_QL_OFF + 128 * 124)
#define SC_KL_OFF (SC_KH_OFF + 64 * 124)
#define SC_SS_OFF (SC_KL_OFF + 64 * 124)
#define SC_SMEM ((SC_SS_OFF + 128 * 66) * 4)   // 224256 B

__global__ __launch_bounds__(256, 1) void score_kernel(
    const int* __restrict__ mask, float* __restrict__ attn)
{
    extern __shared__ float sm[];
    float* Qh = sm;
    float* Ql = sm + SC_QL_OFF;
    float* Kh = sm + SC_KH_OFF;
    float* Kl = sm + SC_KL_OFF;
    float* Ss = sm + SC_SS_OFF;

    const int b  = blockIdx.y;
    const int i0 = blockIdx.x * 128;
    const int tid  = threadIdx.x;
    const int wid  = tid >> 5;
    const int lane = tid & 31;
    const int g    = lane >> 2;
    const int tig  = lane & 3;
    const int m0 = 32 * (wid >> 1);
    const int n0 = 32 * (wid & 1);

    // stage Q (split once, resident)
    {
        const float* gq = g_Q + ((size_t)(b * N1C + i0)) * DD;
        #pragma unroll
        for (int it = 0; it < 16; it++) {
            int idx = it * 256 + tid;
            int r = idx >> 5, ch = idx & 31;
            if (ch < 30) {
                float4 v = *(const float4*)&gq[(size_t)r * DD + ch * 4];
                float4 h, l;
                tsplit(v.x, h.x, l.x); tsplit(v.y, h.y, l.y);
                tsplit(v.z, h.z, l.z); tsplit(v.w, h.w, l.w);
                *(float4*)&Qh[r * 124 + ch * 4] = h;
                *(float4*)&Ql[r * 124 + ch * 4] = l;
            }
        }
    }

    const float scale = 0.09128709291752768f;  // 1/sqrt(120)
    float mrun[16], lrun[16];
    #pragma unroll
    for (int k = 0; k < 16; k++) { mrun[k] = -CUDART_INF_F; lrun[k] = 0.f; }

    for (int t = 0; t < 32; t++) {
        const int j0 = t * 64;
        __syncthreads();
        // stage K tile (split)
        {
            const float* gk = g_K + ((size_t)(b * N2C + j0)) * DD;
            #pragma unroll
            for (int it = 0; it < 8; it++) {
                int idx = it * 256 + tid;
                int r = idx >> 5, ch = idx & 31;
                if (ch < 30) {
                    float4 v = *(const float4*)&gk[(size_t)r * DD + ch * 4];
                    float4 h, l;
                    tsplit(v.x, h.x, l.x); tsplit(v.y, h.y, l.y);
                    tsplit(v.z, h.z, l.z); tsplit(v.w, h.w, l.w);
                    *(float4*)&Kh[r * 124 + ch * 4] = h;
                    *(float4*)&Kl[r * 124 + ch * 4] = l;
                }
            }
        }
        __syncthreads();

        float acc[2][4][4];
        #pragma unroll
        for (int m = 0; m < 2; m++)
            #pragma unroll
            for (int n = 0; n < 4; n++)
                #pragma unroll
                for (int q = 0; q < 4; q++) acc[m][n][q] = 0.f;

        #pragma unroll 5
        for (int k8 = 0; k8 < 15; k8++) {
            const int k0 = k8 * 8;
            uint32_t ah[2][4], al[2][4];
            #pragma unroll
            for (int m = 0; m < 2; m++) {
                int r0 = (m0 + 16 * m + g) * 124 + k0 + tig;
                int r1 = (m0 + 16 * m + 8 + g) * 124 + k0 + tig;
                ah[m][0] = __float_as_uint(Qh[r0]);
                ah[m][1] = __float_as_uint(Qh[r1]);
                ah[m][2] = __float_as_uint(Qh[r0 + 4]);
                ah[m][3] = __float_as_uint(Qh[r1 + 4]);
                al[m][0] = __float_as_uint(Ql[r0]);
                al[m][1] = __float_as_uint(Ql[r1]);
                al[m][2] = __float_as_uint(Ql[r0 + 4]);
                al[m][3] = __float_as_uint(Ql[r1 + 4]);
            }
            #pragma unroll
            for (int n = 0; n < 4; n++) {
                int kb = (n0 + 8 * n + g) * 124 + k0 + tig;
                uint32_t bh0 = __float_as_uint(Kh[kb]);
                uint32_t bh1 = __float_as_uint(Kh[kb + 4]);
                uint32_t bl0 = __float_as_uint(Kl[kb]);
                uint32_t bl1 = __float_as_uint(Kl[kb + 4]);
                #pragma unroll
                for (int m = 0; m < 2; m++) {
                    mma_tf32(acc[m][n], ah[m][0], ah[m][1], ah[m][2], ah[m][3], bh0, bh1);
                    mma_tf32(acc[m][n], al[m][0], al[m][1], al[m][2], al[m][3], bh0, bh1);
                    mma_tf32(acc[m][n], ah[m][0], ah[m][1], ah[m][2], ah[m][3], bl0, bl1);
                }
            }
        }

        // stage D to Ss
        #pragma unroll
        for (int m = 0; m < 2; m++)
            #pragma unroll
            for (int n = 0; n < 4; n++) {
                int row = m0 + 16 * m + g;
                int col = n0 + 8 * n + 2 * tig;
                *(float2*)&Ss[row * 66 + col]       = make_float2(acc[m][n][0], acc[m][n][1]);
                *(float2*)&Ss[(row + 8) * 66 + col] = make_float2(acc[m][n][2], acc[m][n][3]);
            }
        __syncthreads();

        // mask + scale + online stats + raw-score store
        #pragma unroll
        for (int k = 0; k < 16; k++) {
            int r = (k << 3) + wid;
            int gi = i0 + r;
            size_t mb = ((size_t)(b * N1C + gi)) * N2C + j0;
            float raw0 = Ss[r * 66 + lane];
            float raw1 = Ss[r * 66 + 32 + lane];
            int mv0 = mask[mb + lane];
            int mv1 = mask[mb + 32 + lane];
            float s0 = mv0 ? raw0 * scale : -CUDART_INF_F;
            float s1 = mv1 ? raw1 * scale : -CUDART_INF_F;
            attn[mb + lane]      = s0;
            attn[mb + 32 + lane] = s1;

            float tmax = fmaxf(s0, s1);
            #pragma unroll
            for (int o = 16; o; o >>= 1)
                tmax = fmaxf(tmax, __shfl_xor_sync(0xffffffffu, tmax, o));
            float mnew = fmaxf(mrun[k], tmax);

            float se = __expf(s0 - mnew) + __expf(s1 - mnew);
            #pragma unroll
            for (int o = 16; o; o >>= 1)
                se += __shfl_xor_sync(0xffffffffu, se, o);

            lrun[k] = lrun[k] * __expf(mrun[k] - mnew) + se;
            mrun[k] = mnew;
        }
    }

    if (lane == 0) {
        #pragma unroll
        for (int k = 0; k < 16; k++) {
            int gi = b * N1C + i0 + (k << 3) + wid;
            g_M[gi] = mrun[k];
            g_L[gi] = lrun[k];
        }
    }
}

// ================= kernel 3: P normalize + O = P.V via bf16 split mma =================
// smem (uint32 words): Ph[128][36], Pl[128][36], Vh[128][36], Vl[128][36], mrow[128], lirow[128]
#define PV_PL_OFF (128 * 36)
#define PV_VH_OFF (PV_PL_OFF + 128 * 36)
#define PV_VL_OFF (PV_VH_OFF + 128 * 36)
#define PV_MR_OFF (PV_VL_OFF + 128 * 36)
#define PV_SMEM ((PV_MR_OFF + 256) * 4)

__global__ __launch_bounds__(256, 1) void pv_kernel(
    float* __restrict__ attn, float* __restrict__ out)
{
    extern __shared__ float sm[];
    uint32_t* Ph = (uint32_t*)sm;
    uint32_t* Pl = (uint32_t*)sm + PV_PL_OFF;
    uint32_t* Vh = (uint32_t*)sm + PV_VH_OFF;
    uint32_t* Vl = (uint32_t*)sm + PV_VL_OFF;
    float* mrow  = sm + PV_MR_OFF;
    float* lirow = mrow + 128;

    const int b  = blockIdx.y;
    const int i0 = blockIdx.x * 128;
    const int tid  = threadIdx.x;
    const int wid  = tid >> 5;
    const int lane = tid & 31;
    const int g    = lane >> 2;
    const int tig  = lane & 3;
    const int m0 = 32 * (wid >> 1);
    const int e0 = 64 * (wid & 1);

    if (tid < 128) {
        mrow[tid]  = g_M[b * N1C + i0 + tid];
        lirow[tid] = 1.0f / g_L[b * N1C + i0 + tid];
    }
    // zero V rows 120..127 (touched by n=7 fragments of e0=64 warps)
    for (int i = tid; i < 8 * 36; i += 256) {
        Vh[(120 + i / 36) * 36 + (i % 36)] = 0u;
        Vl[(120 + i / 36) * 36 + (i % 36)] = 0u;
    }

    float acc[2][8][4];
    #pragma unroll
    for (int m = 0; m < 2; m++)
        #pragma unroll
        for (int n = 0; n < 8; n++)
            #pragma unroll
            for (int q = 0; q < 4; q++) acc[m][n][q] = 0.f;

    for (int t = 0; t < 32; t++) {
        const int j0 = t * 64;
        __syncthreads();

        // V stage: pack pairs along j at fixed e -> Vh/Vl[e][j2]
        {
            const float* gv = g_V + ((size_t)(b * N2C + j0)) * DD;
            #pragma unroll
            for (int it = 0; it < 15; it++) {
                int idx = it * 256 + tid;     // 32 j2 x 120 e
                int j2 = idx / 120;
                int e  = idx - j2 * 120;
                float v0 = gv[(size_t)(2 * j2) * DD + e];
                float v1 = gv[(size_t)(2 * j2 + 1) * DD + e];
                uint32_t h, l;
                bsplit2(v0, v1, h, l);
                Vh[e * 36 + j2] = h;
                Vl[e * 36 + j2] = l;
            }
        }

        // P stage: raw -> p = exp(s-m)*li; write gmem + pack into Ph/Pl
        #pragma unroll
        for (int it = 0; it < 8; it++) {
            int f4 = it * 256 + tid;          // 128 rows x 16 float4
            int r  = f4 >> 4;
            int c4 = (f4 & 15) * 4;
            size_t gidx = ((size_t)(b * N1C + i0 + r)) * N2C + j0 + c4;
            float4 sv = *(const float4*)&attn[gidx];
            float m = mrow[r], li = lirow[r];
            float4 p;
            p.x = __expf(sv.x - m) * li;
            p.y = __expf(sv.y - m) * li;
            p.z = __expf(sv.z - m) * li;
            p.w = __expf(sv.w - m) * li;
            *(float4*)&attn[gidx] = p;
            uint32_t h0, l0, h1, l1;
            bsplit2(p.x, p.y, h0, l0);
            bsplit2(p.z, p.w, h1, l1);
            int pb = r * 36 + (c4 >> 1);
            Ph[pb] = h0; Ph[pb + 1] = h1;
            Pl[pb] = l0; Pl[pb + 1] = l1;
        }
        __syncthreads();

        // mainloop: 4 k16 chunks over j
        #pragma unroll
        for (int c = 0; c < 4; c++) {
            const int kb2 = c * 8;
            uint32_t ah[2][4], al[2][4];
            #pragma unroll
            for (int m = 0; m < 2; m++) {
                int ra = (m0 + 16 * m + g) * 36 + kb2 + tig;
                int rb = (m0 + 16 * m + 8 + g) * 36 + kb2 + tig;
                ah[m][0] = Ph[ra]; ah[m][1] = Ph[rb];
                ah[m][2] = Ph[ra + 4]; ah[m][3] = Ph[rb + 4];
                al[m][0] = Pl[ra]; al[m][1] = Pl[rb];
                al[m][2] = Pl[ra + 4]; al[m][3] = Pl[rb + 4];
            }
            #pragma unroll
            for (int n = 0; n < 8; n++) {
                int e = e0 + 8 * n + g;
                int vb = e * 36 + kb2 + tig;
                uint32_t bh0 = Vh[vb], bh1 = Vh[vb + 4];
                uint32_t bl0 = Vl[vb], bl1 = Vl[vb + 4];
                #pragma unroll
                for (int m = 0; m < 2; m++) {
                    mma_bf16(acc[m][n], ah[m][0], ah[m][1], ah[m][2], ah[m][3], bh0, bh1);
                    mma_bf16(acc[m][n], al[m][0], al[m][1], al[m][2], al[m][3], bh0, bh1);
                    mma_bf16(acc[m][n], ah[m][0], ah[m][1], ah[m][2], ah[m][3], bl0, bl1);
                }
            }
        }
    }

    // final O store
    #pragma unroll
    for (int m = 0; m < 2; m++)
        #pragma unroll
        for (int n = 0; n < 8; n++) {
            int e = e0 + 8 * n + 2 * tig;
            if (e < DD) {
                int i = i0 + m0 + 16 * m + g;
                *(float2*)&out[((size_t)(b * N1C + i)) * DD + e] =
                    make_float2(acc[m][n][0], acc[m][n][1]);
                *(float2*)&out[((size_t)(b * N1C + i + 8)) * DD + e] =
                    make_float2(acc[m][n][2], acc[m][n][3]);
            }
        }
}

// ================= launch =================
extern "C" void kernel_launch(void* const* d_in, const int* in_sizes, int n_in,
                              void* d_out, int out_size)
{
    const float* x1  = (const float*)d_in[0];
    const float* x2  = (const float*)d_in[1];
    const int*   msk = (const int*)  d_in[2];
    const float* Wq  = (const float*)d_in[3];
    const float* Wk  = (const float*)d_in[4];
    const float* Wv  = (const float*)d_in[5];

    float* outO = (float*)d_out;                    // [B,N1,D]
    float* outP = outO + (size_t)BB * N1C * DD;     // [B,N1,N2]

    cudaFuncSetAttribute(proj_kernel,  cudaFuncAttributeMaxDynamicSharedMemorySize, PROJ_SMEM);
    cudaFuncSetAttribute(score_kernel, cudaFuncAttributeMaxDynamicSharedMemorySize, SC_SMEM);
    cudaFuncSetAttribute(pv_kernel,    cudaFuncAttributeMaxDynamicSharedMemorySize, PV_SMEM);

    proj_kernel <<<dim3((BB * N1C) / 64, 3), 256, PROJ_SMEM>>>(x1, x2, Wq, Wk, Wv);
    score_kernel<<<dim3(N1C / 128, BB), 256, SC_SMEM>>>(msk, outP);
    pv_kernel   <<<dim3(N1C / 128, BB), 256, PV_SMEM>>>(outP, outO);
}

// round 8
// speedup vs baseline: 1.4188x; 1.2619x over previous
#include <cuda_runtime.h>
#include <cuda_bf16.h>
#include <cuda_fp16.h>
#include <math_constants.h>
#include <cstdint>

#define BB 8
#define N1C 2048
#define N2C 2048
#define DD 120

// ---------------- scratch (device globals; no allocation) ----------------
__device__ float    g_Q[(size_t)BB * N1C * DD];          // [b][n1][d]
__device__ float    g_K[(size_t)BB * N2C * DD];          // [b][n2][d]
__device__ uint32_t g_Vh[(size_t)BB * DD * (N2C / 2)];   // [b][e][j2] bf16x2 hi
__device__ uint32_t g_Vl[(size_t)BB * DD * (N2C / 2)];   // [b][e][j2] bf16x2 lo
__device__ float    g_M[BB * N1C];                       // row max
__device__ float    g_L[BB * N1C];                       // row sum-exp

// ---------------- mma helpers ----------------
__device__ __forceinline__ void mma_f16(float* c,
    uint32_t a0, uint32_t a1, uint32_t a2, uint32_t a3,
    uint32_t b0, uint32_t b1)
{
    asm volatile(
        "mma.sync.aligned.m16n8k16.row.col.f32.f16.f16.f32 "
        "{%0,%1,%2,%3}, {%4,%5,%6,%7}, {%8,%9}, {%0,%1,%2,%3};"
        : "+f"(c[0]), "+f"(c[1]), "+f"(c[2]), "+f"(c[3])
        : "r"(a0), "r"(a1), "r"(a2), "r"(a3), "r"(b0), "r"(b1));
}
__device__ __forceinline__ void mma_bf16(float* c,
    uint32_t a0, uint32_t a1, uint32_t a2, uint32_t a3,
    uint32_t b0, uint32_t b1)
{
    asm volatile(
        "mma.sync.aligned.m16n8k16.row.col.f32.bf16.bf16.f32 "
        "{%0,%1,%2,%3}, {%4,%5,%6,%7}, {%8,%9}, {%0,%1,%2,%3};"
        : "+f"(c[0]), "+f"(c[1]), "+f"(c[2]), "+f"(c[3])
        : "r"(a0), "r"(a1), "r"(a2), "r"(a3), "r"(b0), "r"(b1));
}

// two fp32 -> packed fp16x2 hi + fp16x2 lo (x0 in low half)
__device__ __forceinline__ void hsplit2(float x0, float x1, uint32_t& h, uint32_t& l) {
    __half2 hh = __floats2half2_rn(x0, x1);
    float2 hf = __half22float2(hh);
    __half2 ll = __floats2half2_rn(x0 - hf.x, x1 - hf.y);
    h = *(uint32_t*)&hh;
    l = *(uint32_t*)&ll;
}
// two fp32 -> packed bf16x2 hi + bf16x2 lo
__device__ __forceinline__ void bsplit2(float x0, float x1, uint32_t& h, uint32_t& l) {
    __nv_bfloat162 hh = __floats2bfloat162_rn(x0, x1);
    float h0 = __bfloat162float(hh.x), h1 = __bfloat162float(hh.y);
    __nv_bfloat162 ll = __floats2bfloat162_rn(x0 - h0, x1 - h1);
    h = *(uint32_t*)&hh;
    l = *(uint32_t*)&ll;
}

// ================= kernel 1: QKV projection =================
#define PROJ_XS  (64 * 40)
#define PROJ_WS  (40 * 132)
#define PROJ_SMEM ((PROJ_XS + PROJ_WS) * 4)

__global__ __launch_bounds__(256) void proj_kernel(
    const float* __restrict__ x1, const float* __restrict__ x2,
    const float* __restrict__ Wq, const float* __restrict__ Wk,
    const float* __restrict__ Wv)
{
    extern __shared__ float sm[];
    float* Xs = sm;               // [r][40]
    float* Ws = sm + PROJ_XS;     // [d][132]

    const int which = blockIdx.y;
    const float* X = (which == 0) ? x1 : x2;
    const float* W = (which == 0) ? Wq : (which == 1 ? Wk : Wv);

    const int row0 = blockIdx.x * 64;
    const int tid = threadIdx.x;
    const int tx = tid & 15, ty = tid >> 4;

    float acc[4][8];
    #pragma unroll
    for (int r = 0; r < 4; r++)
        #pragma unroll
        for (int c = 0; c < 8; c++) acc[r][c] = 0.f;

    for (int d0 = 0; d0 < DD; d0 += 40) {
        __syncthreads();
        #pragma unroll
        for (int t = 0; t < 10; t++) {
            int idx = t * 256 + tid;
            int r = idx / 40, d = idx % 40;
            Xs[idx] = X[(size_t)(row0 + r) * DD + d0 + d];
        }
        #pragma unroll
        for (int t = 0; t < 20; t++) {
            int idx = t * 256 + tid;
            int d = idx >> 7, e = idx & 127;
            Ws[d * 132 + e] = (e < DD) ? W[(size_t)(d0 + d) * DD + e] : 0.f;
        }
        __syncthreads();

        #pragma unroll 4
        for (int d = 0; d < 40; d++) {
            float4 wa = *(const float4*)&Ws[d * 132 + 4 * tx];
            float4 wb = *(const float4*)&Ws[d * 132 + 64 + 4 * tx];
            float xv[4];
            #pragma unroll
            for (int r = 0; r < 4; r++) xv[r] = Xs[(4 * ty + r) * 40 + d];
            #pragma unroll
            for (int r = 0; r < 4; r++) {
                acc[r][0] = fmaf(xv[r], wa.x, acc[r][0]);
                acc[r][1] = fmaf(xv[r], wa.y, acc[r][1]);
                acc[r][2] = fmaf(xv[r], wa.z, acc[r][2]);
                acc[r][3] = fmaf(xv[r], wa.w, acc[r][3]);
                acc[r][4] = fmaf(xv[r], wb.x, acc[r][4]);
                acc[r][5] = fmaf(xv[r], wb.y, acc[r][5]);
                acc[r][6] = fmaf(xv[r], wb.z, acc[r][6]);
                acc[r][7] = fmaf(xv[r], wb.w, acc[r][7]);
            }
        }
    }

    if (which == 2) {
        // V: pre-split into packed bf16x2 pairs along n2
        const int bb  = row0 >> 11;
        const int n0p = (row0 & 2047) >> 1;
        #pragma unroll
        for (int cc = 0; cc < 8; cc++) {
            int e = (cc < 4) ? (4 * tx + cc) : (64 + 4 * tx + (cc - 4));
            if (e < DD) {
                uint32_t h0, l0, h1, l1;
                bsplit2(acc[0][cc], acc[1][cc], h0, l0);
                bsplit2(acc[2][cc], acc[3][cc], h1, l1);
                size_t base = ((size_t)bb * DD + e) * (N2C / 2) + n0p + 2 * ty;
                g_Vh[base]     = h0;
                g_Vh[base + 1] = h1;
                g_Vl[base]     = l0;
                g_Vl[base + 1] = l1;
            }
        }
    } else {
        float* OUT = (which == 0) ? g_Q : g_K;
        #pragma unroll
        for (int r = 0; r < 4; r++) {
            size_t base = (size_t)(row0 + 4 * ty + r) * DD;
            *(float4*)&OUT[base + 4 * tx] =
                make_float4(acc[r][0], acc[r][1], acc[r][2], acc[r][3]);
            if (64 + 4 * tx + 3 < DD)
                *(float4*)&OUT[base + 64 + 4 * tx] =
                    make_float4(acc[r][4], acc[r][5], acc[r][6], acc[r][7]);
        }
    }
}

// ================= kernel 2: scores via fp16 split mma (k16) =================
// smem word offsets: Qh[128][68], Ql[128][68], Kh[64][68], Kl[64][68], Ss f32[128][68]
#define SC_QH 0
#define SC_QL 8704
#define SC_KH 17408
#define SC_KL 21760
#define SC_SS 26112
#define SC_SMEM ((SC_SS + 128 * 68) * 4)   // 139264 B

__global__ __launch_bounds__(256, 1) void score_kernel(
    const int* __restrict__ mask, float* __restrict__ attn)
{
    extern __shared__ float smf[];
    uint32_t* Qh = (uint32_t*)smf + SC_QH;
    uint32_t* Ql = (uint32_t*)smf + SC_QL;
    uint32_t* Kh = (uint32_t*)smf + SC_KH;
    uint32_t* Kl = (uint32_t*)smf + SC_KL;
    float*    Ss = smf + SC_SS;

    const int b  = blockIdx.y;
    const int i0 = blockIdx.x * 128;
    const int tid  = threadIdx.x;
    const int wid  = tid >> 5;
    const int lane = tid & 31;
    const int g    = lane >> 2;
    const int tig  = lane & 3;
    const int m0 = 32 * (wid >> 1);
    const int n0 = 32 * (wid & 1);

    // zero pads (words 60..63) once; stages only write words < 60
    for (int idx = tid; idx < 512; idx += 256) {
        int r = idx >> 2, w = 60 + (idx & 3);
        Qh[r * 68 + w] = 0u; Ql[r * 68 + w] = 0u;
    }
    if (tid < 256) {
        int r = tid >> 2, w = 60 + (tid & 3);
        Kh[r * 68 + w] = 0u; Kl[r * 68 + w] = 0u;
    }

    // stage Q: split into fp16 hi/lo pairs
    {
        const float* gq = g_Q + ((size_t)(b * N1C + i0)) * DD;
        #pragma unroll
        for (int it = 0; it < 16; it++) {
            int idx = it * 256 + tid;
            int r = idx >> 5, ch = idx & 31;
            if (ch < 30) {
                float4 v = *(const float4*)&gq[(size_t)r * DD + ch * 4];
                uint32_t h0, l0, h1, l1;
                hsplit2(v.x, v.y, h0, l0);
                hsplit2(v.z, v.w, h1, l1);
                int base = r * 68 + ch * 2;
                Qh[base] = h0; Qh[base + 1] = h1;
                Ql[base] = l0; Ql[base + 1] = l1;
            }
        }
    }

    const float scale = 0.09128709291752768f;  // 1/sqrt(120)
    const int halfid = lane >> 4;       // epilogue: 0,1
    const int c4ep   = (lane & 15) * 4; // epilogue col group
    float mrun[8], lrun[8];
    #pragma unroll
    for (int k = 0; k < 8; k++) { mrun[k] = -CUDART_INF_F; lrun[k] = 0.f; }

    for (int t = 0; t < 32; t++) {
        const int j0 = t * 64;
        __syncthreads();
        // stage K tile (fp16 split)
        {
            const float* gk = g_K + ((size_t)(b * N2C + j0)) * DD;
            #pragma unroll
            for (int it = 0; it < 8; it++) {
                int idx = it * 256 + tid;
                int r = idx >> 5, ch = idx & 31;
                if (ch < 30) {
                    float4 v = *(const float4*)&gk[(size_t)r * DD + ch * 4];
                    uint32_t h0, l0, h1, l1;
                    hsplit2(v.x, v.y, h0, l0);
                    hsplit2(v.z, v.w, h1, l1);
                    int base = r * 68 + ch * 2;
                    Kh[base] = h0; Kh[base + 1] = h1;
                    Kl[base] = l0; Kl[base + 1] = l1;
                }
            }
        }
        __syncthreads();

        float acc[2][4][4];
        #pragma unroll
        for (int m = 0; m < 2; m++)
            #pragma unroll
            for (int n = 0; n < 4; n++)
                #pragma unroll
                for (int q = 0; q < 4; q++) acc[m][n][q] = 0.f;

        #pragma unroll
        for (int c = 0; c < 8; c++) {
            const int kw = c * 8 + tig;
            uint32_t ah[2][4], al[2][4];
            #pragma unroll
            for (int m = 0; m < 2; m++) {
                int r0 = (m0 + 16 * m + g) * 68 + kw;
                int r1 = r0 + 8 * 68;
                ah[m][0] = Qh[r0]; ah[m][1] = Qh[r1];
                ah[m][2] = Qh[r0 + 4]; ah[m][3] = Qh[r1 + 4];
                al[m][0] = Ql[r0]; al[m][1] = Ql[r1];
                al[m][2] = Ql[r0 + 4]; al[m][3] = Ql[r1 + 4];
            }
            #pragma unroll
            for (int n = 0; n < 4; n++) {
                int kb = (n0 + 8 * n + g) * 68 + kw;
                uint32_t bh0 = Kh[kb], bh1 = Kh[kb + 4];
                uint32_t bl0 = Kl[kb], bl1 = Kl[kb + 4];
                #pragma unroll
                for (int m = 0; m < 2; m++) {
                    mma_f16(acc[m][n], ah[m][0], ah[m][1], ah[m][2], ah[m][3], bh0, bh1);
                    mma_f16(acc[m][n], al[m][0], al[m][1], al[m][2], al[m][3], bh0, bh1);
                    mma_f16(acc[m][n], ah[m][0], ah[m][1], ah[m][2], ah[m][3], bl0, bl1);
                }
            }
        }

        // stage D to Ss
        #pragma unroll
        for (int m = 0; m < 2; m++)
            #pragma unroll
            for (int n = 0; n < 4; n++) {
                int row = m0 + 16 * m + g;
                int col = n0 + 8 * n + 2 * tig;
                *(float2*)&Ss[row * 68 + col]       = make_float2(acc[m][n][0], acc[m][n][1]);
                *(float2*)&Ss[(row + 8) * 68 + col] = make_float2(acc[m][n][2], acc[m][n][3]);
            }
        __syncthreads();

        // epilogue: float4-wide mask + scale + per-lane online stats + store
        #pragma unroll
        for (int k = 0; k < 8; k++) {
            int r = k * 16 + wid * 2 + halfid;
            float4 sv = *(const float4*)&Ss[r * 68 + c4ep];
            size_t mb = ((size_t)(b * N1C + i0 + r)) * N2C + j0 + c4ep;
            int4 mv = *(const int4*)&mask[mb];
            float4 s;
            s.x = mv.x ? sv.x * scale : -CUDART_INF_F;
            s.y = mv.y ? sv.y * scale : -CUDART_INF_F;
            s.z = mv.z ? sv.z * scale : -CUDART_INF_F;
            s.w = mv.w ? sv.w * scale : -CUDART_INF_F;
            *(float4*)&attn[mb] = s;

            float tmax = fmaxf(fmaxf(s.x, s.y), fmaxf(s.z, s.w));
            float mnew = fmaxf(mrun[k], tmax);
            float rescale = __expf(fmaxf(mrun[k] - mnew, -88.f));
            lrun[k] = lrun[k] * rescale
                    + __expf(s.x - mnew) + __expf(s.y - mnew)
                    + __expf(s.z - mnew) + __expf(s.w - mnew);
            mrun[k] = mnew;
        }
    }

    // final cross-lane merge (16 lanes share a row) + stats write
    #pragma unroll
    for (int k = 0; k < 8; k++) {
        float m = mrun[k], l = lrun[k];
        #pragma unroll
        for (int o = 8; o; o >>= 1) {
            float mo = __shfl_xor_sync(0xffffffffu, m, o);
            float lo = __shfl_xor_sync(0xffffffffu, l, o);
            float mn = fmaxf(m, mo);
            l = l * __expf(fmaxf(m - mn, -88.f)) + lo * __expf(fmaxf(mo - mn, -88.f));
            m = mn;
        }
        if ((lane & 15) == 0) {
            int gi = b * N1C + i0 + k * 16 + wid * 2 + halfid;
            g_M[gi] = m;
            g_L[gi] = l;
        }
    }
}

// ================= kernel 3: P normalize + O = P.V via bf16 split mma =================
// smem (uint32 words): Ph[128][36], Pl[128][36], Vh[128][36], Vl[128][36], mrow[128], lirow[128]
#define PV_PL_OFF (128 * 36)
#define PV_VH_OFF (PV_PL_OFF + 128 * 36)
#define PV_VL_OFF (PV_VH_OFF + 128 * 36)
#define PV_MR_OFF (PV_VL_OFF + 128 * 36)
#define PV_SMEM ((PV_MR_OFF + 256) * 4)

__global__ __launch_bounds__(256, 1) void pv_kernel(
    float* __restrict__ attn, float* __restrict__ out)
{
    extern __shared__ float sm[];
    uint32_t* Ph = (uint32_t*)sm;
    uint32_t* Pl = (uint32_t*)sm + PV_PL_OFF;
    uint32_t* Vh = (uint32_t*)sm + PV_VH_OFF;
    uint32_t* Vl = (uint32_t*)sm + PV_VL_OFF;
    float* mrow  = sm + PV_MR_OFF;
    float* lirow = mrow + 128;

    const int b  = blockIdx.y;
    const int i0 = blockIdx.x * 128;
    const int tid  = threadIdx.x;
    const int wid  = tid >> 5;
    const int lane = tid & 31;
    const int g    = lane >> 2;
    const int tig  = lane & 3;
    const int m0 = 32 * (wid >> 1);
    const int e0 = 64 * (wid & 1);

    if (tid < 128) {
        mrow[tid]  = g_M[b * N1C + i0 + tid];
        lirow[tid] = 1.0f / g_L[b * N1C + i0 + tid];
    }
    // zero V rows 120..127 (touched by n=7 fragments of e0=64 warps)
    for (int i = tid; i < 8 * 36; i += 256) {
        Vh[(120 + i / 36) * 36 + (i % 36)] = 0u;
        Vl[(120 + i / 36) * 36 + (i % 36)] = 0u;
    }

    float acc[2][8][4];
    #pragma unroll
    for (int m = 0; m < 2; m++)
        #pragma unroll
        for (int n = 0; n < 8; n++)
            #pragma unroll
            for (int q = 0; q < 4; q++) acc[m][n][q] = 0.f;

    for (int t = 0; t < 32; t++) {
        const int j0 = t * 64;
        __syncthreads();

        // V stage: plain copy of pre-split pairs
        {
            const uint32_t* gvh = g_Vh + ((size_t)b * DD) * (N2C / 2) + (j0 >> 1);
            const uint32_t* gvl = g_Vl + ((size_t)b * DD) * (N2C / 2) + (j0 >> 1);
            #pragma unroll
            for (int it = 0; it < 15; it++) {
                int idx = it * 256 + tid;     // 120 e x 32 j2
                int e = idx >> 5, j2 = idx & 31;
                Vh[e * 36 + j2] = gvh[(size_t)e * (N2C / 2) + j2];
                Vl[e * 36 + j2] = gvl[(size_t)e * (N2C / 2) + j2];
            }
        }

        // P stage: raw -> p = exp(s-m)*li; write gmem + pack into Ph/Pl
        #pragma unroll
        for (int it = 0; it < 8; it++) {
            int f4 = it * 256 + tid;          // 128 rows x 16 float4
            int r  = f4 >> 4;
            int c4 = (f4 & 15) * 4;
            size_t gidx = ((size_t)(b * N1C + i0 + r)) * N2C + j0 + c4;
            float4 sv = *(const float4*)&attn[gidx];
            float m = mrow[r], li = lirow[r];
            float4 p;
            p.x = __expf(sv.x - m) * li;
            p.y = __expf(sv.y - m) * li;
            p.z = __expf(sv.z - m) * li;
            p.w = __expf(sv.w - m) * li;
            *(float4*)&attn[gidx] = p;
            uint32_t h0, l0, h1, l1;
            bsplit2(p.x, p.y, h0, l0);
            bsplit2(p.z, p.w, h1, l1);
            int pb = r * 36 + (c4 >> 1);
            Ph[pb] = h0; Ph[pb + 1] = h1;
            Pl[pb] = l0; Pl[pb + 1] = l1;
        }
        __syncthreads();

        // mainloop: 4 k16 chunks over j
        #pragma unroll
        for (int c = 0; c < 4; c++) {
            const int kb2 = c * 8;
            uint32_t ah[2][4], al[2][4];
            #pragma unroll
            for (int m = 0; m < 2; m++) {
                int ra = (m0 + 16 * m + g) * 36 + kb2 + tig;
                int rb = (m0 + 16 * m + 8 + g) * 36 + kb2 + tig;
                ah[m][0] = Ph[ra]; ah[m][1] = Ph[rb];
                ah[m][2] = Ph[ra + 4]; ah[m][3] = Ph[rb + 4];
                al[m][0] = Pl[ra]; al[m][1] = Pl[rb];
                al[m][2] = Pl[ra + 4]; al[m][3] = Pl[rb + 4];
            }
            #pragma unroll
            for (int n = 0; n < 8; n++) {
                int e = e0 + 8 * n + g;
                int vb = e * 36 + kb2 + tig;
                uint32_t bh0 = Vh[vb], bh1 = Vh[vb + 4];
                uint32_t bl0 = Vl[vb], bl1 = Vl[vb + 4];
                #pragma unroll
                for (int m = 0; m < 2; m++) {
                    mma_bf16(acc[m][n], ah[m][0], ah[m][1], ah[m][2], ah[m][3], bh0, bh1);
                    mma_bf16(acc[m][n], al[m][0], al[m][1], al[m][2], al[m][3], bh0, bh1);
                    mma_bf16(acc[m][n], ah[m][0], ah[m][1], ah[m][2], ah[m][3], bl0, bl1);
                }
            }
        }
    }

    // final O store
    #pragma unroll
    for (int m = 0; m < 2; m++)
        #pragma unroll
        for (int n = 0; n < 8; n++) {
            int e = e0 + 8 * n + 2 * tig;
            if (e < DD) {
                int i = i0 + m0 + 16 * m + g;
                *(float2*)&out[((size_t)(b * N1C + i)) * DD + e] =
                    make_float2(acc[m][n][0], acc[m][n][1]);
                *(float2*)&out[((size_t)(b * N1C + i + 8)) * DD + e] =
                    make_float2(acc[m][n][2], acc[m][n][3]);
            }
        }
}

// ================= launch =================
extern "C" void kernel_launch(void* const* d_in, const int* in_sizes, int n_in,
                              void* d_out, int out_size)
{
    const float* x1  = (const float*)d_in[0];
    const float* x2  = (const float*)d_in[1];
    const int*   msk = (const int*)  d_in[2];
    const float* Wq  = (const float*)d_in[3];
    const float* Wk  = (const float*)d_in[4];
    const float* Wv  = (const float*)d_in[5];

    float* outO = (float*)d_out;                    // [B,N1,D]
    float* outP = outO + (size_t)BB * N1C * DD;     // [B,N1,N2]

    cudaFuncSetAttribute(proj_kernel,  cudaFuncAttributeMaxDynamicSharedMemorySize, PROJ_SMEM);
    cudaFuncSetAttribute(score_kernel, cudaFuncAttributeMaxDynamicSharedMemorySize, SC_SMEM);
    cudaFuncSetAttribute(pv_kernel,    cudaFuncAttributeMaxDynamicSharedMemorySize, PV_SMEM);

    proj_kernel <<<dim3((BB * N1C) / 64, 3), 256, PROJ_SMEM>>>(x1, x2, Wq, Wk, Wv);
    score_kernel<<<dim3(N1C / 128, BB), 256, SC_SMEM>>>(msk, outP);
    pv_kernel   <<<dim3(N1C / 128, BB), 256, PV_SMEM>>>(outP, outO);
}